// round 13
// baseline (speedup 1.0000x reference)
#include <cuda_runtime.h>
#include <cuda_bf16.h>
#include <stdint.h>

#define NNODES 100000
#define NEDGES 300000
#define DIM    256
#define D4     64
#define LAYERS 5

// ================= GEMM tiling: BK=16, deep pipelined =================
#define BM 64
#define BN 256
#define BK 16
#define APITCH 40     // 80B rows, conflict-free ldsm
#define BPITCH 264    // 528B rows; conflict-free trans ldsm

#define A_PLANE (BM * APITCH)        // 2560 elems
#define A_STAGE (2 * A_PLANE)        // 10240 B
#define B_PLANE (BK * BPITCH)        // 4224 elems
#define B_STAGE (2 * B_PLANE)        // 8448 elems
#define BBYTES  (B_STAGE * 2)        // 16896 B
#define B_RING 4
// gemm1: A ring 3 (uses 2), B ring 4  -> 30720 + 67584 = 98304
#define SMEM_G1 (3 * A_STAGE * 2 + B_RING * BBYTES)
// gemm2: A ring 4, B ring 4          -> 40960 + 67584 = 108544
#define SMEM_G2 (4 * A_STAGE * 2 + B_RING * BBYTES)

// ---------------- scratch ----------------
__device__ __align__(16) float g_cur[(size_t)NNODES * DIM];
__device__ __align__(16) float g_agg[(size_t)NNODES * DIM];
__device__ __align__(16) float g_h  [(size_t)NNODES * DIM];
__device__ __align__(16) __nv_bfloat16 g_h1h[(size_t)NNODES * 2 * DIM];
__device__ __align__(16) __nv_bfloat16 g_h1l[(size_t)NNODES * 2 * DIM];
__device__ __align__(16) __nv_bfloat16 g_w1p[LAYERS * 2 * 16 * B_STAGE];
__device__ __align__(16) __nv_bfloat16 g_w2p[LAYERS * 32 * B_STAGE];
__device__ __align__(16) float g_sum[DIM];
__device__ __align__(16) float g_sumsq[DIM];
__device__ __align__(16) float g_scale[DIM];
__device__ __align__(16) float g_shift[DIM];

// ---------------- helpers ----------------
__device__ __forceinline__ uint32_t cvta_s(const void* p) {
    return (uint32_t)__cvta_generic_to_shared(p);
}
__device__ __forceinline__ uint32_t bpack(__nv_bfloat16 a, __nv_bfloat16 b) {
    __nv_bfloat162 t(a, b);
    return reinterpret_cast<uint32_t&>(t);
}
__device__ __forceinline__ void split4(float4 v, uint2& hi, uint2& lo) {
    float a[4] = {v.x, v.y, v.z, v.w};
    __nv_bfloat16 h[4], l[4];
#pragma unroll
    for (int j = 0; j < 4; j++) {
        h[j] = __float2bfloat16(a[j]);
        l[j] = __float2bfloat16(a[j] - __bfloat162float(h[j]));
    }
    hi = make_uint2(bpack(h[0], h[1]), bpack(h[2], h[3]));
    lo = make_uint2(bpack(l[0], l[1]), bpack(l[2], l[3]));
}
__device__ __forceinline__ void ldsm4(uint32_t r[4], uint32_t a) {
    asm volatile("ldmatrix.sync.aligned.m8n8.x4.shared.b16 {%0,%1,%2,%3}, [%4];"
                 : "=r"(r[0]), "=r"(r[1]), "=r"(r[2]), "=r"(r[3]) : "r"(a));
}
__device__ __forceinline__ void ldsm4t(uint32_t r[4], uint32_t a) {
    asm volatile("ldmatrix.sync.aligned.m8n8.x4.trans.shared.b16 {%0,%1,%2,%3}, [%4];"
                 : "=r"(r[0]), "=r"(r[1]), "=r"(r[2]), "=r"(r[3]) : "r"(a));
}
__device__ __forceinline__ void mma_bf16(float c[4], const uint32_t a[4], const uint32_t b[2]) {
    asm volatile("mma.sync.aligned.m16n8k16.row.col.f32.bf16.bf16.f32 "
                 "{%0,%1,%2,%3}, {%4,%5,%6,%7}, {%8,%9}, {%0,%1,%2,%3};"
                 : "+f"(c[0]), "+f"(c[1]), "+f"(c[2]), "+f"(c[3])
                 : "r"(a[0]), "r"(a[1]), "r"(a[2]), "r"(a[3]), "r"(b[0]), "r"(b[1]));
}
__device__ __forceinline__ void cp16(uint32_t dst, const void* src, bool pred) {
    int sz = pred ? 16 : 0;
    asm volatile("cp.async.cg.shared.global [%0], [%1], 16, %2;"
                 :: "r"(dst), "l"(src), "r"(sz));
}
__device__ __forceinline__ void cp_commit() { asm volatile("cp.async.commit_group;"); }
__device__ __forceinline__ void mbar_init(uint32_t a, uint32_t cnt) {
    asm volatile("mbarrier.init.shared.b64 [%0], %1;" :: "r"(a), "r"(cnt) : "memory");
}
__device__ __forceinline__ void mbar_expect(uint32_t a, uint32_t tx) {
    asm volatile("mbarrier.arrive.expect_tx.shared.b64 _, [%0], %1;"
                 :: "r"(a), "r"(tx) : "memory");
}
__device__ __forceinline__ void bulk_g2s(uint32_t dst, const void* src, uint32_t bytes,
                                         uint32_t bar) {
    asm volatile("cp.async.bulk.shared::cluster.global.mbarrier::complete_tx::bytes "
                 "[%0], [%1], %2, [%3];"
                 :: "r"(dst), "l"(src), "r"(bytes), "r"(bar) : "memory");
}
__device__ __forceinline__ void mbar_wait(uint32_t bar, uint32_t ph) {
    asm volatile("{\n\t.reg .pred P;\n\t"
                 "W%=:\n\t"
                 "mbarrier.try_wait.parity.shared.b64 P, [%0], %1;\n\t"
                 "@P bra D%=;\n\t"
                 "bra W%=;\n\t"
                 "D%=:\n\t}"
                 :: "r"(bar), "r"(ph) : "memory");
}

// ---------------- init nodes + convert weights to padded stage images ----------------
#define C1TOT (LAYERS * 256 * 128)
#define C2TOT (LAYERS * 512 * 64)
__global__ void init_nodes(const int* __restrict__ x,
                           const float* __restrict__ xe1,
                           const float* __restrict__ xe2,
                           const float* __restrict__ W1,
                           const float* __restrict__ W2) {
    int t = blockIdx.x * blockDim.x + threadIdx.x;
    if (t < DIM) { g_sum[t] = 0.f; g_sumsq[t] = 0.f; }
    if (t < C1TOT) {
        int l = t / (256 * 128);
        int r = t % (256 * 128);
        int k = r >> 7;
        int n = (r & 127) * 4;
        float4 v = *(const float4*)(W1 + ((size_t)l * 256 + k) * 512 + n);
        uint2 hi, lo;
        split4(v, hi, lo);
        int xh = n >> 8, st = k >> 4, row = k & 15, c = n & 255;
        size_t base = (((size_t)l * 2 + xh) * 16 + st) * B_STAGE + row * BPITCH + c;
        *(uint2*)(g_w1p + base) = hi;
        *(uint2*)(g_w1p + base + B_PLANE) = lo;
    } else if (t < C1TOT + C2TOT) {
        int u = t - C1TOT;
        int l = u / (512 * 64);
        int r = u % (512 * 64);
        int k = r >> 6;
        int n = (r & 63) * 4;
        float4 v = *(const float4*)(W2 + ((size_t)l * 512 + k) * 256 + n);
        uint2 hi, lo;
        split4(v, hi, lo);
        int st = k >> 4, row = k & 15;
        size_t base = ((size_t)l * 32 + st) * B_STAGE + row * BPITCH + n;
        *(uint2*)(g_w2p + base) = hi;
        *(uint2*)(g_w2p + base + B_PLANE) = lo;
    }
    if (t >= NNODES * D4) return;
    int n_ = t / D4, c = t % D4;
    int i0 = x[2 * n_ + 0];
    int i1 = x[2 * n_ + 1];
    float4 a = ((const float4*)(xe1 + (size_t)i0 * DIM))[c];
    float4 b = ((const float4*)(xe2 + (size_t)i1 * DIM))[c];
    float4 r;
    r.x = a.x + b.x; r.y = a.y + b.y; r.z = a.z + b.z; r.w = a.w + b.w;
    ((float4*)g_cur)[t] = r;
}

// ---------------- layer0: agg = cur + self-emb ----------------
__global__ void agg_init(const float* __restrict__ e1self,
                         const float* __restrict__ e2self) {
    int t = blockIdx.x * blockDim.x + threadIdx.x;
    if (t >= NNODES * D4) return;
    int c = t % D4;
    float4 v = ((const float4*)g_cur)[t];
    float4 a = __ldg(&((const float4*)e1self)[c]);
    float4 b = __ldg(&((const float4*)e2self)[c]);
    v.x += a.x + b.x; v.y += a.y + b.y; v.z += a.z + b.z; v.w += a.w + b.w;
    ((float4*)g_agg)[t] = v;
}

// ---------------- layers>=1: agg = relu(bn(h)) + self-emb ----------------
__global__ void agg_self_bn(const float* __restrict__ e1self,
                            const float* __restrict__ e2self) {
    int t = blockIdx.x * blockDim.x + threadIdx.x;
    if (t >= NNODES * D4) return;
    int c = t % D4;
    float4 v = ((const float4*)g_h)[t];
    float4 sc = ((const float4*)g_scale)[c];
    float4 sh = ((const float4*)g_shift)[c];
    float4 a = __ldg(&((const float4*)e1self)[c]);
    float4 b = __ldg(&((const float4*)e2self)[c]);
    float4 r;
    r.x = fmaxf(v.x * sc.x + sh.x, 0.f) + a.x + b.x;
    r.y = fmaxf(v.y * sc.y + sh.y, 0.f) + a.y + b.y;
    r.z = fmaxf(v.z * sc.z + sh.z, 0.f) + a.z + b.z;
    r.w = fmaxf(v.w * sc.w + sh.w, 0.f) + a.w + b.w;
    ((float4*)g_agg)[t] = r;
}

// ---------------- edge messages ----------------
template <bool BN_>
__global__ void edge_msg(const int* __restrict__ ei,
                         const int* __restrict__ ea,
                         const float* __restrict__ ee1,
                         const float* __restrict__ ee2) {
    int gtid = blockIdx.x * blockDim.x + threadIdx.x;
    int e = gtid >> 5;
    int lane = gtid & 31;
    if (e >= NEDGES) return;
    int src = ei[e];
    int dst = ei[NEDGES + e];
    int a0 = ea[2 * e + 0];
    int a1 = ea[2 * e + 1];
    const float4* sp = (const float4*)((BN_ ? g_h : g_cur) + (size_t)src * DIM);
    const float4* e1p = (const float4*)(ee1 + (size_t)a0 * DIM);
    const float4* e2p = (const float4*)(ee2 + (size_t)a1 * DIM);
    float* dp = g_agg + (size_t)dst * DIM;
#pragma unroll
    for (int j = 0; j < 2; j++) {
        int c = lane + j * 32;
        float4 v = sp[c];
        if (BN_) {
            float4 sc = __ldg(&((const float4*)g_scale)[c]);
            float4 sh = __ldg(&((const float4*)g_shift)[c]);
            v.x = fmaxf(v.x * sc.x + sh.x, 0.f);
            v.y = fmaxf(v.y * sc.y + sh.y, 0.f);
            v.z = fmaxf(v.z * sc.z + sh.z, 0.f);
            v.w = fmaxf(v.w * sc.w + sh.w, 0.f);
        }
        float4 w = __ldg(&e1p[c]);
        float4 u = __ldg(&e2p[c]);
        v.x += w.x + u.x; v.y += w.y + u.y; v.z += w.z + u.z; v.w += w.w + u.w;
        asm volatile("red.global.add.v4.f32 [%0], {%1, %2, %3, %4};"
                     :: "l"(dp + c * 4), "f"(v.x), "f"(v.y), "f"(v.z), "f"(v.w)
                     : "memory");
    }
}

// -------- compute one BK=16 stage (R9 pairing) --------
__device__ __forceinline__ void gemm_stage_compute(
    uint32_t sAb, uint32_t sBb, int aBuf, int bBuf,
    int aR, int aKb, int bK, int bNl, int warpN,
    float acc[2][8][4]) {
    uint32_t af[2][2][4];
#pragma unroll
    for (int mi = 0; mi < 2; mi++)
#pragma unroll
        for (int p = 0; p < 2; p++) {
            uint32_t addr = sAb +
                (uint32_t)((aBuf * A_STAGE + p * A_PLANE + (aR + mi * 16) * APITCH) * 2 + aKb);
            ldsm4(af[mi][p], addr);
        }
#pragma unroll
    for (int gp = 0; gp < 2; gp++) {
        uint32_t bh[2][4], bl[2][4];
#pragma unroll
        for (int q = 0; q < 2; q++) {
            int g = gp * 2 + q;
            int n0 = warpN * 64 + g * 16 + bNl;
            ldsm4t(bh[q], sBb + (uint32_t)((bBuf * B_STAGE + bK * BPITCH + n0) * 2));
            ldsm4t(bl[q], sBb + (uint32_t)((bBuf * B_STAGE + B_PLANE + bK * BPITCH + n0) * 2));
        }
#pragma unroll
        for (int q = 0; q < 2; q++)
#pragma unroll
            for (int mi = 0; mi < 2; mi++)
#pragma unroll
                for (int nn = 0; nn < 2; nn++)
                    mma_bf16(acc[mi][(gp * 2 + q) * 2 + nn], af[mi][0], &bh[q][nn * 2]);
#pragma unroll
        for (int q = 0; q < 2; q++)
#pragma unroll
            for (int mi = 0; mi < 2; mi++)
#pragma unroll
                for (int nn = 0; nn < 2; nn++)
                    mma_bf16(acc[mi][(gp * 2 + q) * 2 + nn], af[mi][0], &bl[q][nn * 2]);
#pragma unroll
        for (int q = 0; q < 2; q++)
#pragma unroll
            for (int mi = 0; mi < 2; mi++)
#pragma unroll
                for (int nn = 0; nn < 2; nn++)
                    mma_bf16(acc[mi][(gp * 2 + q) * 2 + nn], af[mi][1], &bh[q][nn * 2]);
    }
}

// ================= GEMM1: unchanged from R12 =================
__global__ __launch_bounds__(256, 2)
void gemm1(const float* __restrict__ A,
           const __nv_bfloat16* __restrict__ Bp,
           const float* __restrict__ bias,
           __nv_bfloat16* __restrict__ Ch, __nv_bfloat16* __restrict__ Cl,
           int M, int N, int K) {
    extern __shared__ __align__(16) char dynsm[];
    __shared__ __align__(8) uint64_t sbar[B_RING];
    const uint32_t sAb = cvta_s(dynsm);
    const uint32_t sBb = sAb + 3 * A_STAGE * 2;
    const int tid  = threadIdx.x;
    const int lane = tid & 31;
    const int warp = tid >> 5;
    const int warpM = warp & 1;
    const int warpN = warp >> 1;
    const int rowBase = blockIdx.y * BM;
    const int colBase = blockIdx.x * BN;
    const int S = K / BK;   // 16

    const char* Bsrc = (const char*)(Bp + (size_t)blockIdx.x * 16 * B_STAGE);

    const int aR  = warpM * 32 + (lane & 7) + ((lane >> 3) & 1) * 8;
    const int aKb = (lane >> 4) * 16;
    const int bK  = (lane & 7) + ((lane >> 3) & 1) * 8;
    const int bNl = ((lane >> 4) & 1) * 8;

    const int aRow = tid >> 2;
    const int aC4  = (tid & 3) * 4;
    const bool aOk = (rowBase + aRow) < M;
    const float* aPtr = A + (size_t)(rowBase + aRow) * K + aC4;
    const uint32_t aOffBase = (uint32_t)(aRow * APITCH + aC4) * 2;

    float acc[2][8][4];
#pragma unroll
    for (int i = 0; i < 2; i++)
#pragma unroll
        for (int j = 0; j < 8; j++)
#pragma unroll
            for (int k = 0; k < 4; k++) acc[i][j][k] = 0.f;

    if (tid == 0) {
#pragma unroll
        for (int i = 0; i < B_RING; i++) mbar_init(cvta_s(&sbar[i]), 1);
    }

    float4 aV = aOk ? *(const float4*)(aPtr) : make_float4(0, 0, 0, 0);
    {
        uint2 hi, lo;
        split4(aV, hi, lo);
        *(uint2*)(dynsm + aOffBase) = hi;
        *(uint2*)(dynsm + aOffBase + A_PLANE * 2) = lo;
    }
    aV = aOk ? *(const float4*)(aPtr + BK) : make_float4(0, 0, 0, 0);
    if (tid == 0) {
#pragma unroll
        for (int st = 0; st < 3; st++) {
            mbar_expect(cvta_s(&sbar[st]), BBYTES);
            bulk_g2s(sBb + st * BBYTES, Bsrc + (size_t)st * BBYTES, BBYTES, cvta_s(&sbar[st]));
        }
    }

    for (int s = 0; s < S; s++) {
        int aBuf = s & 1;
        int bBuf = s & 3;
        if (tid == 0) mbar_wait(cvta_s(&sbar[bBuf]), (s >> 2) & 1);
        __syncthreads();
        if (s + 1 < S) {
            uint32_t off = (uint32_t)((aBuf ^ 1) * A_STAGE) * 2 + aOffBase;
            uint2 hi, lo;
            split4(aV, hi, lo);
            *(uint2*)(dynsm + off) = hi;
            *(uint2*)(dynsm + off + A_PLANE * 2) = lo;
            if (s + 2 < S)
                aV = aOk ? *(const float4*)(aPtr + (s + 2) * BK) : make_float4(0, 0, 0, 0);
        }
        if (tid == 0 && s + 3 < S) {
            int st = s + 3, rb = st & 3;
            mbar_expect(cvta_s(&sbar[rb]), BBYTES);
            bulk_g2s(sBb + rb * BBYTES, Bsrc + (size_t)st * BBYTES, BBYTES, cvta_s(&sbar[rb]));
        }
        gemm_stage_compute(sAb, sBb, aBuf, bBuf, aR, aKb, bK, bNl, warpN, acc);
    }

    const int r0b = rowBase + warpM * 32 + (lane >> 2);
    const int cb  = colBase + warpN * 64 + (lane & 3) * 2;
    float bb[16];
#pragma unroll
    for (int ni = 0; ni < 8; ni++) {
        bb[2 * ni]     = __ldg(&bias[cb + ni * 8]);
        bb[2 * ni + 1] = __ldg(&bias[cb + ni * 8 + 1]);
    }
#pragma unroll
    for (int mi = 0; mi < 2; mi++) {
        int r0 = r0b + mi * 16;
        int r1 = r0 + 8;
#pragma unroll
        for (int ni = 0; ni < 8; ni++) {
            int c = cb + ni * 8;
            float2 v0 = make_float2(fmaxf(acc[mi][ni][0] + bb[2 * ni], 0.f),
                                    fmaxf(acc[mi][ni][1] + bb[2 * ni + 1], 0.f));
            float2 v1 = make_float2(fmaxf(acc[mi][ni][2] + bb[2 * ni], 0.f),
                                    fmaxf(acc[mi][ni][3] + bb[2 * ni + 1], 0.f));
            if (r0 < M) {
                __nv_bfloat16 hx = __float2bfloat16(v0.x), hy = __float2bfloat16(v0.y);
                *(uint32_t*)(Ch + (size_t)r0 * N + c) = bpack(hx, hy);
                *(uint32_t*)(Cl + (size_t)r0 * N + c) =
                    bpack(__float2bfloat16(v0.x - __bfloat162float(hx)),
                          __float2bfloat16(v0.y - __bfloat162float(hy)));
            }
            if (r1 < M) {
                __nv_bfloat16 hx = __float2bfloat16(v1.x), hy = __float2bfloat16(v1.y);
                *(uint32_t*)(Ch + (size_t)r1 * N + c) = bpack(hx, hy);
                *(uint32_t*)(Cl + (size_t)r1 * N + c) =
                    bpack(__float2bfloat16(v1.x - __bfloat162float(hx)),
                          __float2bfloat16(v1.y - __bfloat162float(hy)));
            }
        }
    }
}

// ================= GEMM2: paired stages, 1 sync / 2 stages, per-warp B waits =================
__device__ __forceinline__ void stage_load_A2(
    uint32_t sAb, int buf,
    const __nv_bfloat16* Ah, const __nv_bfloat16* Al,
    int rowBase, int kOff, int K, int M, int tid) {
    int plane = tid >> 7;
    int rem = tid & 127;
    int row = rem >> 1, c8 = (rem & 1) * 8;
    const __nv_bfloat16* src = (plane ? Al : Ah) + (size_t)(rowBase + row) * K + kOff + c8;
    uint32_t dst = sAb + (uint32_t)(buf * A_STAGE + plane * A_PLANE + row * APITCH + c8) * 2;
    cp16(dst, src, (rowBase + row) < M);
}

template <bool FUSE_STATS>
__global__ __launch_bounds__(256, 2)
void gemm2(const __nv_bfloat16* __restrict__ Ah, const __nv_bfloat16* __restrict__ Al,
           const __nv_bfloat16* __restrict__ Bp,
           const float* __restrict__ bias, float* __restrict__ Cf,
           int M, int N, int K) {
    extern __shared__ __align__(16) char dynsm[];
    __shared__ float sStat[512];
    __shared__ __align__(8) uint64_t sbar[B_RING];
    const uint32_t sAb = cvta_s(dynsm);
    const uint32_t sBb = sAb + 4 * A_STAGE * 2;
    const int tid  = threadIdx.x;
    const int lane = tid & 31;
    const int warp = tid >> 5;
    const int warpM = warp & 1;
    const int warpN = warp >> 1;
    const int rowBase = blockIdx.y * BM;
    const int colBase = blockIdx.x * BN;
    const int S = K / BK;   // 32
    const int P = S / 2;    // 16 pairs

    const char* Bsrc = (const char*)Bp;

    if (FUSE_STATS) {
        sStat[tid] = 0.f;
        sStat[256 + tid] = 0.f;
    }

    const int aR  = warpM * 32 + (lane & 7) + ((lane >> 3) & 1) * 8;
    const int aKb = (lane >> 4) * 16;
    const int bK  = (lane & 7) + ((lane >> 3) & 1) * 8;
    const int bNl = ((lane >> 4) & 1) * 8;

    float acc[2][8][4];
#pragma unroll
    for (int i = 0; i < 2; i++)
#pragma unroll
        for (int j = 0; j < 8; j++)
#pragma unroll
            for (int k = 0; k < 4; k++) acc[i][j][k] = 0.f;

    if (tid == 0) {
#pragma unroll
        for (int i = 0; i < B_RING; i++) mbar_init(cvta_s(&sbar[i]), 1);
    }

    // prologue: A pair0 (slots 0,1); B(0),B(1)
    stage_load_A2(sAb, 0, Ah, Al, rowBase, 0, K, M, tid);
    stage_load_A2(sAb, 1, Ah, Al, rowBase, BK, K, M, tid);
    cp_commit();
    if (tid == 0) {
        mbar_expect(cvta_s(&sbar[0]), BBYTES);
        bulk_g2s(sBb, Bsrc, BBYTES, cvta_s(&sbar[0]));
        mbar_expect(cvta_s(&sbar[1]), BBYTES);
        bulk_g2s(sBb + BBYTES, Bsrc + (size_t)BBYTES, BBYTES, cvta_s(&sbar[1]));
    }

    for (int p = 0; p < P; p++) {
        int s0 = 2 * p;
        asm volatile("cp.async.wait_group 0;");  // A(pair p) landed (this thread)
        __syncthreads();                          // publish A(pair p); pair p-1 compute done
        if (p + 1 < P) {
            // A pair p+1 -> slots (s0+2)&3, (s0+3)&3 (last read at pair p-1)
            stage_load_A2(sAb, (s0 + 2) & 3, Ah, Al, rowBase, (s0 + 2) * BK, K, M, tid);
            stage_load_A2(sAb, (s0 + 3) & 3, Ah, Al, rowBase, (s0 + 3) * BK, K, M, tid);
            cp_commit();
            if (tid == 0) {
                // B pair p+1 -> slots (s0+2)&3, (s0+3)&3
                int rb2 = (s0 + 2) & 3, rb3 = (s0 + 3) & 3;
                mbar_expect(cvta_s(&sbar[rb2]), BBYTES);
                bulk_g2s(sBb + rb2 * BBYTES, Bsrc + (size_t)(s0 + 2) * BBYTES, BBYTES,
                         cvta_s(&sbar[rb2]));
                mbar_expect(cvta_s(&sbar[rb3]), BBYTES);
                bulk_g2s(sBb + rb3 * BBYTES, Bsrc + (size_t)(s0 + 3) * BBYTES, BBYTES,
                         cvta_s(&sbar[rb3]));
            }
        }
        // per-warp: wait B(s0), compute; wait B(s0+1), compute — warps drift here
        mbar_wait(cvta_s(&sbar[s0 & 3]), (s0 >> 2) & 1);
        gemm_stage_compute(sAb, sBb, s0 & 3, s0 & 3, aR, aKb, bK, bNl, warpN, acc);
        mbar_wait(cvta_s(&sbar[(s0 + 1) & 3]), ((s0 + 1) >> 2) & 1);
        gemm_stage_compute(sAb, sBb, (s0 + 1) & 3, (s0 + 1) & 3, aR, aKb, bK, bNl, warpN, acc);
    }

    const int r0b = rowBase + warpM * 32 + (lane >> 2);
    const int cb  = colBase + warpN * 64 + (lane & 3) * 2;
    float bb[16];
#pragma unroll
    for (int ni = 0; ni < 8; ni++) {
        bb[2 * ni]     = __ldg(&bias[cb + ni * 8]);
        bb[2 * ni + 1] = __ldg(&bias[cb + ni * 8 + 1]);
    }
#pragma unroll
    for (int mi = 0; mi < 2; mi++) {
        int r0 = r0b + mi * 16;
        int r1 = r0 + 8;
#pragma unroll
        for (int ni = 0; ni < 8; ni++) {
            int c = cb + ni * 8;
            float2 v0 = make_float2(acc[mi][ni][0] + bb[2 * ni], acc[mi][ni][1] + bb[2 * ni + 1]);
            float2 v1 = make_float2(acc[mi][ni][2] + bb[2 * ni], acc[mi][ni][3] + bb[2 * ni + 1]);
            if (FUSE_STATS) {
                float ax = (r0 < M) ? v0.x : 0.f;
                float ay = (r0 < M) ? v0.y : 0.f;
                float bx2 = (r1 < M) ? v1.x : 0.f;
                float by2 = (r1 < M) ? v1.y : 0.f;
                float sc0 = ax + bx2, sc1 = ay + by2;
                float q0 = ax * ax + bx2 * bx2, q1 = ay * ay + by2 * by2;
#pragma unroll
                for (int off = 4; off <= 16; off <<= 1) {
                    sc0 += __shfl_xor_sync(0xFFFFFFFF, sc0, off);
                    sc1 += __shfl_xor_sync(0xFFFFFFFF, sc1, off);
                    q0  += __shfl_xor_sync(0xFFFFFFFF, q0, off);
                    q1  += __shfl_xor_sync(0xFFFFFFFF, q1, off);
                }
                if ((lane >> 2) == 0) {
                    atomicAdd(&sStat[c - colBase], sc0);
                    atomicAdd(&sStat[c - colBase + 1], sc1);
                    atomicAdd(&sStat[256 + c - colBase], q0);
                    atomicAdd(&sStat[256 + c - colBase + 1], q1);
                }
            }
            if (r0 < M) *(float2*)(Cf + (size_t)r0 * N + c) = v0;
            if (r1 < M) *(float2*)(Cf + (size_t)r1 * N + c) = v1;
        }
    }

    if (FUSE_STATS) {
        __syncthreads();
        if (tid < 256) {
            atomicAdd(&g_sum[tid], sStat[tid]);
            atomicAdd(&g_sumsq[tid], sStat[256 + tid]);
        }
    }
}

// ---------------- BN finalize (+ re-zero for next layer) ----------------
__global__ void bn_finalize(const float* __restrict__ gamma,
                            const float* __restrict__ beta) {
    int d = threadIdx.x;
    float mean = g_sum[d] * (1.0f / NNODES);
    float var = g_sumsq[d] * (1.0f / NNODES) - mean * mean;
    float sc = gamma[d] * rsqrtf(var + 1e-5f);
    g_scale[d] = sc;
    g_shift[d] = beta[d] - mean * sc;
    g_sum[d] = 0.f;
    g_sumsq[d] = 0.f;
}

// ---------------- launch ----------------
extern "C" void kernel_launch(void* const* d_in, const int* in_sizes, int n_in,
                              void* d_out, int out_size) {
    const int*   x   = (const int*)d_in[0];
    const int*   ei  = (const int*)d_in[1];
    const int*   ea  = (const int*)d_in[2];
    const float* xe1 = (const float*)d_in[3];
    const float* xe2 = (const float*)d_in[4];
    const float* ee1 = (const float*)d_in[5];
    const float* ee2 = (const float*)d_in[6];
    const float* W1  = (const float*)d_in[7];
    const float* b1  = (const float*)d_in[8];
    const float* W2  = (const float*)d_in[9];
    const float* b2  = (const float*)d_in[10];
    const float* gam = (const float*)d_in[11];
    const float* bet = (const float*)d_in[12];
    float* out = (float*)d_out;

    __nv_bfloat16 *p_h1h, *p_h1l, *p_w1p, *p_w2p;
    float *p_h, *p_agg;
    cudaGetSymbolAddress((void**)&p_h1h, g_h1h);
    cudaGetSymbolAddress((void**)&p_h1l, g_h1l);
    cudaGetSymbolAddress((void**)&p_w1p, g_w1p);
    cudaGetSymbolAddress((void**)&p_w2p, g_w2p);
    cudaGetSymbolAddress((void**)&p_h,   g_h);
    cudaGetSymbolAddress((void**)&p_agg, g_agg);

    cudaFuncSetAttribute(gemm1, cudaFuncAttributeMaxDynamicSharedMemorySize, SMEM_G1);
    cudaFuncSetAttribute(gemm2<true>, cudaFuncAttributeMaxDynamicSharedMemorySize, SMEM_G2);
    cudaFuncSetAttribute(gemm2<false>, cudaFuncAttributeMaxDynamicSharedMemorySize, SMEM_G2);

    const int ELEM_BLOCKS = (NNODES * D4 + 255) / 256;
    const int EDGE_BLOCKS = (NEDGES * 32 + 255) / 256;
    const int MB = (NNODES + BM - 1) / BM;

    init_nodes<<<ELEM_BLOCKS, 256>>>(x, xe1, xe2, W1, W2);

    for (int l = 0; l < LAYERS; l++) {
        const float* e1l = ee1 + (size_t)l * 6 * DIM;
        const float* e2l = ee2 + (size_t)l * 3 * DIM;

        if (l == 0) {
            agg_init<<<ELEM_BLOCKS, 256>>>(e1l + 4 * DIM, e2l);
            edge_msg<false><<<EDGE_BLOCKS, 256>>>(ei, ea, e1l, e2l);
        } else {
            agg_self_bn<<<ELEM_BLOCKS, 256>>>(e1l + 4 * DIM, e2l);
            edge_msg<true><<<EDGE_BLOCKS, 256>>>(ei, ea, e1l, e2l);
        }

        gemm1<<<dim3(2, MB), 256, SMEM_G1>>>(
            p_agg,
            p_w1p + (size_t)l * 2 * 16 * B_STAGE,
            b1 + (size_t)l * 2 * DIM,
            p_h1h, p_h1l, NNODES, 2 * DIM, DIM);

        if (l < LAYERS - 1) {
            gemm2<true><<<dim3(1, MB), 256, SMEM_G2>>>(
                p_h1h, p_h1l,
                p_w2p + (size_t)l * 32 * B_STAGE,
                b2 + (size_t)l * DIM, p_h, NNODES, DIM, 2 * DIM);
            bn_finalize<<<1, 256>>>(gam + (size_t)l * DIM, bet + (size_t)l * DIM);
        } else {
            gemm2<false><<<dim3(1, MB), 256, SMEM_G2>>>(
                p_h1h, p_h1l,
                p_w2p + (size_t)l * 32 * B_STAGE,
                b2 + (size_t)l * DIM, out, NNODES, DIM, 2 * DIM);
        }
    }
}

// round 14
// speedup vs baseline: 1.0074x; 1.0074x over previous
#include <cuda_runtime.h>
#include <cuda_bf16.h>
#include <stdint.h>

#define NNODES 100000
#define NEDGES 300000
#define DIM    256
#define D4     64
#define LAYERS 5

// ================= GEMM tiling: BK=16, deep pipelined =================
#define BM 64
#define BN 256
#define BK 16
#define APITCH 40
#define BPITCH 264

#define A_PLANE (BM * APITCH)
#define A_STAGE (2 * A_PLANE)
#define B_PLANE (BK * BPITCH)
#define B_STAGE (2 * B_PLANE)
#define BBYTES  (B_STAGE * 2)
#define B_RING 4
#define SMEM_G1 (3 * A_STAGE * 2 + B_RING * BBYTES)
#define SMEM_G2 (3 * A_STAGE * 2 + B_RING * BBYTES)

// ---------------- scratch ----------------
__device__ __align__(16) float g_cur[(size_t)NNODES * DIM];
__device__ __align__(16) float g_agg[(size_t)NNODES * DIM];
__device__ __align__(16) float g_h  [(size_t)NNODES * DIM];
__device__ __align__(16) __nv_bfloat16 g_h1h[(size_t)NNODES * 2 * DIM];
__device__ __align__(16) __nv_bfloat16 g_h1l[(size_t)NNODES * 2 * DIM];
__device__ __align__(16) __nv_bfloat16 g_w1p[LAYERS * 2 * 16 * B_STAGE];
__device__ __align__(16) __nv_bfloat16 g_w2p[LAYERS * 32 * B_STAGE];
__device__ __align__(16) float g_sum[DIM];
__device__ __align__(16) float g_sumsq[DIM];
__device__ __align__(16) float g_scale[DIM];
__device__ __align__(16) float g_shift[DIM];

// ---------------- helpers ----------------
__device__ __forceinline__ uint32_t cvta_s(const void* p) {
    return (uint32_t)__cvta_generic_to_shared(p);
}
__device__ __forceinline__ uint32_t bpack(__nv_bfloat16 a, __nv_bfloat16 b) {
    __nv_bfloat162 t(a, b);
    return reinterpret_cast<uint32_t&>(t);
}
__device__ __forceinline__ void split4(float4 v, uint2& hi, uint2& lo) {
    float a[4] = {v.x, v.y, v.z, v.w};
    __nv_bfloat16 h[4], l[4];
#pragma unroll
    for (int j = 0; j < 4; j++) {
        h[j] = __float2bfloat16(a[j]);
        l[j] = __float2bfloat16(a[j] - __bfloat162float(h[j]));
    }
    hi = make_uint2(bpack(h[0], h[1]), bpack(h[2], h[3]));
    lo = make_uint2(bpack(l[0], l[1]), bpack(l[2], l[3]));
}
__device__ __forceinline__ void ldsm4(uint32_t r[4], uint32_t a) {
    asm volatile("ldmatrix.sync.aligned.m8n8.x4.shared.b16 {%0,%1,%2,%3}, [%4];"
                 : "=r"(r[0]), "=r"(r[1]), "=r"(r[2]), "=r"(r[3]) : "r"(a));
}
__device__ __forceinline__ void ldsm4t(uint32_t r[4], uint32_t a) {
    asm volatile("ldmatrix.sync.aligned.m8n8.x4.trans.shared.b16 {%0,%1,%2,%3}, [%4];"
                 : "=r"(r[0]), "=r"(r[1]), "=r"(r[2]), "=r"(r[3]) : "r"(a));
}
__device__ __forceinline__ void mma_bf16(float c[4], const uint32_t a[4], const uint32_t b[2]) {
    asm volatile("mma.sync.aligned.m16n8k16.row.col.f32.bf16.bf16.f32 "
                 "{%0,%1,%2,%3}, {%4,%5,%6,%7}, {%8,%9}, {%0,%1,%2,%3};"
                 : "+f"(c[0]), "+f"(c[1]), "+f"(c[2]), "+f"(c[3])
                 : "r"(a[0]), "r"(a[1]), "r"(a[2]), "r"(a[3]), "r"(b[0]), "r"(b[1]));
}
__device__ __forceinline__ void cp16(uint32_t dst, const void* src, bool pred) {
    int sz = pred ? 16 : 0;
    asm volatile("cp.async.cg.shared.global [%0], [%1], 16, %2;"
                 :: "r"(dst), "l"(src), "r"(sz));
}
__device__ __forceinline__ void cp_commit() { asm volatile("cp.async.commit_group;"); }
__device__ __forceinline__ void mbar_init(uint32_t a, uint32_t cnt) {
    asm volatile("mbarrier.init.shared.b64 [%0], %1;" :: "r"(a), "r"(cnt) : "memory");
}
__device__ __forceinline__ void mbar_expect(uint32_t a, uint32_t tx) {
    asm volatile("mbarrier.arrive.expect_tx.shared.b64 _, [%0], %1;"
                 :: "r"(a), "r"(tx) : "memory");
}
__device__ __forceinline__ void bulk_g2s(uint32_t dst, const void* src, uint32_t bytes,
                                         uint32_t bar) {
    asm volatile("cp.async.bulk.shared::cluster.global.mbarrier::complete_tx::bytes "
                 "[%0], [%1], %2, [%3];"
                 :: "r"(dst), "l"(src), "r"(bytes), "r"(bar) : "memory");
}
// per-warp acquire wait
__device__ __forceinline__ void mbar_wait_acq(uint32_t bar, uint32_t ph) {
    asm volatile("{\n\t.reg .pred P;\n\t"
                 "W%=:\n\t"
                 "mbarrier.try_wait.parity.acquire.cta.shared::cta.b64 P, [%0], %1;\n\t"
                 "@P bra D%=;\n\t"
                 "bra W%=;\n\t"
                 "D%=:\n\t}"
                 :: "r"(bar), "r"(ph) : "memory");
}

// ---------------- init nodes + convert weights to padded stage images ----------------
#define C1TOT (LAYERS * 256 * 128)
#define C2TOT (LAYERS * 512 * 64)
__global__ void init_nodes(const int* __restrict__ x,
                           const float* __restrict__ xe1,
                           const float* __restrict__ xe2,
                           const float* __restrict__ W1,
                           const float* __restrict__ W2) {
    int t = blockIdx.x * blockDim.x + threadIdx.x;
    if (t < DIM) { g_sum[t] = 0.f; g_sumsq[t] = 0.f; }
    if (t < C1TOT) {
        int l = t / (256 * 128);
        int r = t % (256 * 128);
        int k = r >> 7;
        int n = (r & 127) * 4;
        float4 v = *(const float4*)(W1 + ((size_t)l * 256 + k) * 512 + n);
        uint2 hi, lo;
        split4(v, hi, lo);
        int xh = n >> 8, st = k >> 4, row = k & 15, c = n & 255;
        size_t base = (((size_t)l * 2 + xh) * 16 + st) * B_STAGE + row * BPITCH + c;
        *(uint2*)(g_w1p + base) = hi;
        *(uint2*)(g_w1p + base + B_PLANE) = lo;
    } else if (t < C1TOT + C2TOT) {
        int u = t - C1TOT;
        int l = u / (512 * 64);
        int r = u % (512 * 64);
        int k = r >> 6;
        int n = (r & 63) * 4;
        float4 v = *(const float4*)(W2 + ((size_t)l * 512 + k) * 256 + n);
        uint2 hi, lo;
        split4(v, hi, lo);
        int st = k >> 4, row = k & 15;
        size_t base = ((size_t)l * 32 + st) * B_STAGE + row * BPITCH + n;
        *(uint2*)(g_w2p + base) = hi;
        *(uint2*)(g_w2p + base + B_PLANE) = lo;
    }
    if (t >= NNODES * D4) return;
    int n_ = t / D4, c = t % D4;
    int i0 = x[2 * n_ + 0];
    int i1 = x[2 * n_ + 1];
    float4 a = ((const float4*)(xe1 + (size_t)i0 * DIM))[c];
    float4 b = ((const float4*)(xe2 + (size_t)i1 * DIM))[c];
    float4 r;
    r.x = a.x + b.x; r.y = a.y + b.y; r.z = a.z + b.z; r.w = a.w + b.w;
    ((float4*)g_cur)[t] = r;
}

// ---------------- layer0: agg = cur + self-emb ----------------
__global__ void agg_init(const float* __restrict__ e1self,
                         const float* __restrict__ e2self) {
    int t = blockIdx.x * blockDim.x + threadIdx.x;
    if (t >= NNODES * D4) return;
    int c = t % D4;
    float4 v = ((const float4*)g_cur)[t];
    float4 a = __ldg(&((const float4*)e1self)[c]);
    float4 b = __ldg(&((const float4*)e2self)[c]);
    v.x += a.x + b.x; v.y += a.y + b.y; v.z += a.z + b.z; v.w += a.w + b.w;
    ((float4*)g_agg)[t] = v;
}

// ---------------- layers>=1: agg = relu(bn(h)) + self-emb ----------------
__global__ void agg_self_bn(const float* __restrict__ e1self,
                            const float* __restrict__ e2self) {
    int t = blockIdx.x * blockDim.x + threadIdx.x;
    if (t >= NNODES * D4) return;
    int c = t % D4;
    float4 v = ((const float4*)g_h)[t];
    float4 sc = ((const float4*)g_scale)[c];
    float4 sh = ((const float4*)g_shift)[c];
    float4 a = __ldg(&((const float4*)e1self)[c]);
    float4 b = __ldg(&((const float4*)e2self)[c]);
    float4 r;
    r.x = fmaxf(v.x * sc.x + sh.x, 0.f) + a.x + b.x;
    r.y = fmaxf(v.y * sc.y + sh.y, 0.f) + a.y + b.y;
    r.z = fmaxf(v.z * sc.z + sh.z, 0.f) + a.z + b.z;
    r.w = fmaxf(v.w * sc.w + sh.w, 0.f) + a.w + b.w;
    ((float4*)g_agg)[t] = r;
}

// ---------------- edge messages ----------------
template <bool BN_>
__global__ void edge_msg(const int* __restrict__ ei,
                         const int* __restrict__ ea,
                         const float* __restrict__ ee1,
                         const float* __restrict__ ee2) {
    int gtid = blockIdx.x * blockDim.x + threadIdx.x;
    int e = gtid >> 5;
    int lane = gtid & 31;
    if (e >= NEDGES) return;
    int src = ei[e];
    int dst = ei[NEDGES + e];
    int a0 = ea[2 * e + 0];
    int a1 = ea[2 * e + 1];
    const float4* sp = (const float4*)((BN_ ? g_h : g_cur) + (size_t)src * DIM);
    const float4* e1p = (const float4*)(ee1 + (size_t)a0 * DIM);
    const float4* e2p = (const float4*)(ee2 + (size_t)a1 * DIM);
    float* dp = g_agg + (size_t)dst * DIM;
#pragma unroll
    for (int j = 0; j < 2; j++) {
        int c = lane + j * 32;
        float4 v = sp[c];
        if (BN_) {
            float4 sc = __ldg(&((const float4*)g_scale)[c]);
            float4 sh = __ldg(&((const float4*)g_shift)[c]);
            v.x = fmaxf(v.x * sc.x + sh.x, 0.f);
            v.y = fmaxf(v.y * sc.y + sh.y, 0.f);
            v.z = fmaxf(v.z * sc.z + sh.z, 0.f);
            v.w = fmaxf(v.w * sc.w + sh.w, 0.f);
        }
        float4 w = __ldg(&e1p[c]);
        float4 u = __ldg(&e2p[c]);
        v.x += w.x + u.x; v.y += w.y + u.y; v.z += w.z + u.z; v.w += w.w + u.w;
        asm volatile("red.global.add.v4.f32 [%0], {%1, %2, %3, %4};"
                     :: "l"(dp + c * 4), "f"(v.x), "f"(v.y), "f"(v.z), "f"(v.w)
                     : "memory");
    }
}

// -------- compute one BK=16 stage (R9 pairing) --------
__device__ __forceinline__ void gemm_stage_compute(
    uint32_t sAb, uint32_t sBb, int aBuf, int bBuf,
    int aR, int aKb, int bK, int bNl, int warpN,
    float acc[2][8][4]) {
    uint32_t af[2][2][4];
#pragma unroll
    for (int mi = 0; mi < 2; mi++)
#pragma unroll
        for (int p = 0; p < 2; p++) {
            uint32_t addr = sAb +
                (uint32_t)((aBuf * A_STAGE + p * A_PLANE + (aR + mi * 16) * APITCH) * 2 + aKb);
            ldsm4(af[mi][p], addr);
        }
#pragma unroll
    for (int gp = 0; gp < 2; gp++) {
        uint32_t bh[2][4], bl[2][4];
#pragma unroll
        for (int q = 0; q < 2; q++) {
            int g = gp * 2 + q;
            int n0 = warpN * 64 + g * 16 + bNl;
            ldsm4t(bh[q], sBb + (uint32_t)((bBuf * B_STAGE + bK * BPITCH + n0) * 2));
            ldsm4t(bl[q], sBb + (uint32_t)((bBuf * B_STAGE + B_PLANE + bK * BPITCH + n0) * 2));
        }
#pragma unroll
        for (int q = 0; q < 2; q++)
#pragma unroll
            for (int mi = 0; mi < 2; mi++)
#pragma unroll
                for (int nn = 0; nn < 2; nn++)
                    mma_bf16(acc[mi][(gp * 2 + q) * 2 + nn], af[mi][0], &bh[q][nn * 2]);
#pragma unroll
        for (int q = 0; q < 2; q++)
#pragma unroll
            for (int mi = 0; mi < 2; mi++)
#pragma unroll
                for (int nn = 0; nn < 2; nn++)
                    mma_bf16(acc[mi][(gp * 2 + q) * 2 + nn], af[mi][0], &bl[q][nn * 2]);
#pragma unroll
        for (int q = 0; q < 2; q++)
#pragma unroll
            for (int mi = 0; mi < 2; mi++)
#pragma unroll
                for (int nn = 0; nn < 2; nn++)
                    mma_bf16(acc[mi][(gp * 2 + q) * 2 + nn], af[mi][1], &bh[q][nn * 2]);
    }
}

// ================= GEMM1: sync -> prefetch -> per-warp B acquire -> compute =================
__global__ __launch_bounds__(256, 2)
void gemm1(const float* __restrict__ A,
           const __nv_bfloat16* __restrict__ Bp,
           const float* __restrict__ bias,
           __nv_bfloat16* __restrict__ Ch, __nv_bfloat16* __restrict__ Cl,
           int M, int N, int K) {
    extern __shared__ __align__(16) char dynsm[];
    __shared__ __align__(8) uint64_t sbar[B_RING];
    const uint32_t sAb = cvta_s(dynsm);
    const uint32_t sBb = sAb + 3 * A_STAGE * 2;
    const int tid  = threadIdx.x;
    const int lane = tid & 31;
    const int warp = tid >> 5;
    const int warpM = warp & 1;
    const int warpN = warp >> 1;
    const int rowBase = blockIdx.y * BM;
    const int colBase = blockIdx.x * BN;
    const int S = K / BK;   // 16

    const char* Bsrc = (const char*)(Bp + (size_t)blockIdx.x * 16 * B_STAGE);

    const int aR  = warpM * 32 + (lane & 7) + ((lane >> 3) & 1) * 8;
    const int aKb = (lane >> 4) * 16;
    const int bK  = (lane & 7) + ((lane >> 3) & 1) * 8;
    const int bNl = ((lane >> 4) & 1) * 8;

    const int aRow = tid >> 2;
    const int aC4  = (tid & 3) * 4;
    const bool aOk = (rowBase + aRow) < M;
    const float* aPtr = A + (size_t)(rowBase + aRow) * K + aC4;
    const uint32_t aOffBase = (uint32_t)(aRow * APITCH + aC4) * 2;

    float acc[2][8][4];
#pragma unroll
    for (int i = 0; i < 2; i++)
#pragma unroll
        for (int j = 0; j < 8; j++)
#pragma unroll
            for (int k = 0; k < 4; k++) acc[i][j][k] = 0.f;

    if (tid == 0) {
#pragma unroll
        for (int i = 0; i < B_RING; i++) mbar_init(cvta_s(&sbar[i]), 1);
    }

    float4 aV = aOk ? *(const float4*)(aPtr) : make_float4(0, 0, 0, 0);
    {
        uint2 hi, lo;
        split4(aV, hi, lo);
        *(uint2*)(dynsm + aOffBase) = hi;
        *(uint2*)(dynsm + aOffBase + A_PLANE * 2) = lo;
    }
    aV = aOk ? *(const float4*)(aPtr + BK) : make_float4(0, 0, 0, 0);
    if (tid == 0) {
#pragma unroll
        for (int st = 0; st < 3; st++) {
            mbar_expect(cvta_s(&sbar[st]), BBYTES);
            bulk_g2s(sBb + st * BBYTES, Bsrc + (size_t)st * BBYTES, BBYTES, cvta_s(&sbar[st]));
        }
    }

    for (int s = 0; s < S; s++) {
        int aBuf = s & 1;
        int bBuf = s & 3;
        __syncthreads();   // all warps done compute(s-1): A-buf & B-slot recycle safe; bars init'd
        if (s + 1 < S) {
            uint32_t off = (uint32_t)((aBuf ^ 1) * A_STAGE) * 2 + aOffBase;
            uint2 hi, lo;
            split4(aV, hi, lo);
            *(uint2*)(dynsm + off) = hi;
            *(uint2*)(dynsm + off + A_PLANE * 2) = lo;
            if (s + 2 < S)
                aV = aOk ? *(const float4*)(aPtr + (s + 2) * BK) : make_float4(0, 0, 0, 0);
        }
        if (tid == 0 && s + 3 < S) {
            int st = s + 3, rb = st & 3;
            mbar_expect(cvta_s(&sbar[rb]), BBYTES);
            bulk_g2s(sBb + rb * BBYTES, Bsrc + (size_t)st * BBYTES, BBYTES, cvta_s(&sbar[rb]));
        }
        mbar_wait_acq(cvta_s(&sbar[bBuf]), (s >> 2) & 1);   // per-warp acquire of B(s)
        gemm_stage_compute(sAb, sBb, aBuf, bBuf, aR, aKb, bK, bNl, warpN, acc);
    }

    const int r0b = rowBase + warpM * 32 + (lane >> 2);
    const int cb  = colBase + warpN * 64 + (lane & 3) * 2;
    float bb[16];
#pragma unroll
    for (int ni = 0; ni < 8; ni++) {
        bb[2 * ni]     = __ldg(&bias[cb + ni * 8]);
        bb[2 * ni + 1] = __ldg(&bias[cb + ni * 8 + 1]);
    }
#pragma unroll
    for (int mi = 0; mi < 2; mi++) {
        int r0 = r0b + mi * 16;
        int r1 = r0 + 8;
#pragma unroll
        for (int ni = 0; ni < 8; ni++) {
            int c = cb + ni * 8;
            float2 v0 = make_float2(fmaxf(acc[mi][ni][0] + bb[2 * ni], 0.f),
                                    fmaxf(acc[mi][ni][1] + bb[2 * ni + 1], 0.f));
            float2 v1 = make_float2(fmaxf(acc[mi][ni][2] + bb[2 * ni], 0.f),
                                    fmaxf(acc[mi][ni][3] + bb[2 * ni + 1], 0.f));
            if (r0 < M) {
                __nv_bfloat16 hx = __float2bfloat16(v0.x), hy = __float2bfloat16(v0.y);
                *(uint32_t*)(Ch + (size_t)r0 * N + c) = bpack(hx, hy);
                *(uint32_t*)(Cl + (size_t)r0 * N + c) =
                    bpack(__float2bfloat16(v0.x - __bfloat162float(hx)),
                          __float2bfloat16(v0.y - __bfloat162float(hy)));
            }
            if (r1 < M) {
                __nv_bfloat16 hx = __float2bfloat16(v1.x), hy = __float2bfloat16(v1.y);
                *(uint32_t*)(Ch + (size_t)r1 * N + c) = bpack(hx, hy);
                *(uint32_t*)(Cl + (size_t)r1 * N + c) =
                    bpack(__float2bfloat16(v1.x - __bfloat162float(hx)),
                          __float2bfloat16(v1.y - __bfloat162float(hy)));
            }
        }
    }
}

// ================= GEMM2: R12 loop + per-warp B acquire =================
__device__ __forceinline__ void stage_load_A2(
    uint32_t sAb, int buf,
    const __nv_bfloat16* Ah, const __nv_bfloat16* Al,
    int rowBase, int kOff, int K, int M, int tid) {
    int plane = tid >> 7;
    int rem = tid & 127;
    int row = rem >> 1, c8 = (rem & 1) * 8;
    const __nv_bfloat16* src = (plane ? Al : Ah) + (size_t)(rowBase + row) * K + kOff + c8;
    uint32_t dst = sAb + (uint32_t)(buf * A_STAGE + plane * A_PLANE + row * APITCH + c8) * 2;
    cp16(dst, src, (rowBase + row) < M);
}

template <bool FUSE_STATS>
__global__ __launch_bounds__(256, 2)
void gemm2(const __nv_bfloat16* __restrict__ Ah, const __nv_bfloat16* __restrict__ Al,
           const __nv_bfloat16* __restrict__ Bp,
           const float* __restrict__ bias, float* __restrict__ Cf,
           int M, int N, int K) {
    extern __shared__ __align__(16) char dynsm[];
    __shared__ float sStat[512];
    __shared__ __align__(8) uint64_t sbar[B_RING];
    const uint32_t sAb = cvta_s(dynsm);
    const uint32_t sBb = sAb + 3 * A_STAGE * 2;
    const int tid  = threadIdx.x;
    const int lane = tid & 31;
    const int warp = tid >> 5;
    const int warpM = warp & 1;
    const int warpN = warp >> 1;
    const int rowBase = blockIdx.y * BM;
    const int colBase = blockIdx.x * BN;
    const int S = K / BK;   // 32

    const char* Bsrc = (const char*)Bp;

    if (FUSE_STATS) {
        sStat[tid] = 0.f;
        sStat[256 + tid] = 0.f;
    }

    const int aR  = warpM * 32 + (lane & 7) + ((lane >> 3) & 1) * 8;
    const int aKb = (lane >> 4) * 16;
    const int bK  = (lane & 7) + ((lane >> 3) & 1) * 8;
    const int bNl = ((lane >> 4) & 1) * 8;

    float acc[2][8][4];
#pragma unroll
    for (int i = 0; i < 2; i++)
#pragma unroll
        for (int j = 0; j < 8; j++)
#pragma unroll
            for (int k = 0; k < 4; k++) acc[i][j][k] = 0.f;

    if (tid == 0) {
#pragma unroll
        for (int i = 0; i < B_RING; i++) mbar_init(cvta_s(&sbar[i]), 1);
    }

    stage_load_A2(sAb, 0, Ah, Al, rowBase, 0, K, M, tid);
    cp_commit();
    stage_load_A2(sAb, 1, Ah, Al, rowBase, BK, K, M, tid);
    cp_commit();
    if (tid == 0) {
#pragma unroll
        for (int st = 0; st < 3; st++) {
            mbar_expect(cvta_s(&sbar[st]), BBYTES);
            bulk_g2s(sBb + st * BBYTES, Bsrc + (size_t)st * BBYTES, BBYTES, cvta_s(&sbar[st]));
        }
    }

    for (int s = 0; s < S; s++) {
        int aBuf = s % 3;
        int bBuf = s & 3;
        if (s + 1 < S) asm volatile("cp.async.wait_group 1;");
        else           asm volatile("cp.async.wait_group 0;");
        __syncthreads();   // A(s) published; compute(s-1) done -> slot recycle safe
        if (s + 2 < S) {
            stage_load_A2(sAb, (s + 2) % 3, Ah, Al, rowBase, (s + 2) * BK, K, M, tid);
            cp_commit();
        }
        if (tid == 0 && s + 3 < S) {
            int st = s + 3, rb = st & 3;
            mbar_expect(cvta_s(&sbar[rb]), BBYTES);
            bulk_g2s(sBb + rb * BBYTES, Bsrc + (size_t)st * BBYTES, BBYTES, cvta_s(&sbar[rb]));
        }
        mbar_wait_acq(cvta_s(&sbar[bBuf]), (s >> 2) & 1);   // per-warp acquire of B(s)
        gemm_stage_compute(sAb, sBb, aBuf, bBuf, aR, aKb, bK, bNl, warpN, acc);
    }

    const int r0b = rowBase + warpM * 32 + (lane >> 2);
    const int cb  = colBase + warpN * 64 + (lane & 3) * 2;
    float bb[16];
#pragma unroll
    for (int ni = 0; ni < 8; ni++) {
        bb[2 * ni]     = __ldg(&bias[cb + ni * 8]);
        bb[2 * ni + 1] = __ldg(&bias[cb + ni * 8 + 1]);
    }
#pragma unroll
    for (int mi = 0; mi < 2; mi++) {
        int r0 = r0b + mi * 16;
        int r1 = r0 + 8;
#pragma unroll
        for (int ni = 0; ni < 8; ni++) {
            int c = cb + ni * 8;
            float2 v0 = make_float2(acc[mi][ni][0] + bb[2 * ni], acc[mi][ni][1] + bb[2 * ni + 1]);
            float2 v1 = make_float2(acc[mi][ni][2] + bb[2 * ni], acc[mi][ni][3] + bb[2 * ni + 1]);
            if (FUSE_STATS) {
                float ax = (r0 < M) ? v0.x : 0.f;
                float ay = (r0 < M) ? v0.y : 0.f;
                float bx2 = (r1 < M) ? v1.x : 0.f;
                float by2 = (r1 < M) ? v1.y : 0.f;
                float sc0 = ax + bx2, sc1 = ay + by2;
                float q0 = ax * ax + bx2 * bx2, q1 = ay * ay + by2 * by2;
#pragma unroll
                for (int off = 4; off <= 16; off <<= 1) {
                    sc0 += __shfl_xor_sync(0xFFFFFFFF, sc0, off);
                    sc1 += __shfl_xor_sync(0xFFFFFFFF, sc1, off);
                    q0  += __shfl_xor_sync(0xFFFFFFFF, q0, off);
                    q1  += __shfl_xor_sync(0xFFFFFFFF, q1, off);
                }
                if ((lane >> 2) == 0) {
                    atomicAdd(&sStat[c - colBase], sc0);
                    atomicAdd(&sStat[c - colBase + 1], sc1);
                    atomicAdd(&sStat[256 + c - colBase], q0);
                    atomicAdd(&sStat[256 + c - colBase + 1], q1);
                }
            }
            if (r0 < M) *(float2*)(Cf + (size_t)r0 * N + c) = v0;
            if (r1 < M) *(float2*)(Cf + (size_t)r1 * N + c) = v1;
        }
    }

    if (FUSE_STATS) {
        __syncthreads();
        if (tid < 256) {
            atomicAdd(&g_sum[tid], sStat[tid]);
            atomicAdd(&g_sumsq[tid], sStat[256 + tid]);
        }
    }
}

// ---------------- BN finalize (+ re-zero for next layer) ----------------
__global__ void bn_finalize(const float* __restrict__ gamma,
                            const float* __restrict__ beta) {
    int d = threadIdx.x;
    float mean = g_sum[d] * (1.0f / NNODES);
    float var = g_sumsq[d] * (1.0f / NNODES) - mean * mean;
    float sc = gamma[d] * rsqrtf(var + 1e-5f);
    g_scale[d] = sc;
    g_shift[d] = beta[d] - mean * sc;
    g_sum[d] = 0.f;
    g_sumsq[d] = 0.f;
}

// ---------------- launch ----------------
extern "C" void kernel_launch(void* const* d_in, const int* in_sizes, int n_in,
                              void* d_out, int out_size) {
    const int*   x   = (const int*)d_in[0];
    const int*   ei  = (const int*)d_in[1];
    const int*   ea  = (const int*)d_in[2];
    const float* xe1 = (const float*)d_in[3];
    const float* xe2 = (const float*)d_in[4];
    const float* ee1 = (const float*)d_in[5];
    const float* ee2 = (const float*)d_in[6];
    const float* W1  = (const float*)d_in[7];
    const float* b1  = (const float*)d_in[8];
    const float* W2  = (const float*)d_in[9];
    const float* b2  = (const float*)d_in[10];
    const float* gam = (const float*)d_in[11];
    const float* bet = (const float*)d_in[12];
    float* out = (float*)d_out;

    __nv_bfloat16 *p_h1h, *p_h1l, *p_w1p, *p_w2p;
    float *p_h, *p_agg;
    cudaGetSymbolAddress((void**)&p_h1h, g_h1h);
    cudaGetSymbolAddress((void**)&p_h1l, g_h1l);
    cudaGetSymbolAddress((void**)&p_w1p, g_w1p);
    cudaGetSymbolAddress((void**)&p_w2p, g_w2p);
    cudaGetSymbolAddress((void**)&p_h,   g_h);
    cudaGetSymbolAddress((void**)&p_agg, g_agg);

    cudaFuncSetAttribute(gemm1, cudaFuncAttributeMaxDynamicSharedMemorySize, SMEM_G1);
    cudaFuncSetAttribute(gemm2<true>, cudaFuncAttributeMaxDynamicSharedMemorySize, SMEM_G2);
    cudaFuncSetAttribute(gemm2<false>, cudaFuncAttributeMaxDynamicSharedMemorySize, SMEM_G2);

    const int ELEM_BLOCKS = (NNODES * D4 + 255) / 256;
    const int EDGE_BLOCKS = (NEDGES * 32 + 255) / 256;
    const int MB = (NNODES + BM - 1) / BM;

    init_nodes<<<ELEM_BLOCKS, 256>>>(x, xe1, xe2, W1, W2);

    for (int l = 0; l < LAYERS; l++) {
        const float* e1l = ee1 + (size_t)l * 6 * DIM;
        const float* e2l = ee2 + (size_t)l * 3 * DIM;

        if (l == 0) {
            agg_init<<<ELEM_BLOCKS, 256>>>(e1l + 4 * DIM, e2l);
            edge_msg<false><<<EDGE_BLOCKS, 256>>>(ei, ea, e1l, e2l);
        } else {
            agg_self_bn<<<ELEM_BLOCKS, 256>>>(e1l + 4 * DIM, e2l);
            edge_msg<true><<<EDGE_BLOCKS, 256>>>(ei, ea, e1l, e2l);
        }

        gemm1<<<dim3(2, MB), 256, SMEM_G1>>>(
            p_agg,
            p_w1p + (size_t)l * 2 * 16 * B_STAGE,
            b1 + (size_t)l * 2 * DIM,
            p_h1h, p_h1l, NNODES, 2 * DIM, DIM);

        if (l < LAYERS - 1) {
            gemm2<true><<<dim3(1, MB), 256, SMEM_G2>>>(
                p_h1h, p_h1l,
                p_w2p + (size_t)l * 32 * B_STAGE,
                b2 + (size_t)l * DIM, p_h, NNODES, DIM, 2 * DIM);
            bn_finalize<<<1, 256>>>(gam + (size_t)l * DIM, bet + (size_t)l * DIM);
        } else {
            gemm2<false><<<dim3(1, MB), 256, SMEM_G2>>>(
                p_h1h, p_h1l,
                p_w2p + (size_t)l * 32 * B_STAGE,
                b2 + (size_t)l * DIM, out, NNODES, DIM, 2 * DIM);
        }
    }
}

// round 15
// speedup vs baseline: 1.0304x; 1.0228x over previous
#include <cuda_runtime.h>
#include <cuda_bf16.h>
#include <stdint.h>

#define NNODES 100000
#define NEDGES 300000
#define DIM    256
#define D4     64
#define LAYERS 5

// ================= GEMM tiling: BK=16, deep pipelined =================
#define BM 64
#define BN 256
#define BK 16
#define APITCH 40
#define BPITCH 264

#define A_PLANE (BM * APITCH)
#define A_STAGE (2 * A_PLANE)
#define B_PLANE (BK * BPITCH)
#define B_STAGE (2 * B_PLANE)
#define BBYTES  (B_STAGE * 2)
#define B_RING 4
#define SMEM_G1 (3 * A_STAGE * 2 + B_RING * BBYTES)
#define SMEM_G2 (3 * A_STAGE * 2 + B_RING * BBYTES)

// ---------------- scratch ----------------
__device__ __align__(16) float g_cur[(size_t)NNODES * DIM];
__device__ __align__(16) float g_agg[(size_t)NNODES * DIM];
__device__ __align__(16) float g_h  [(size_t)NNODES * DIM];
__device__ __align__(16) __nv_bfloat16 g_h1h[(size_t)NNODES * 2 * DIM];
__device__ __align__(16) __nv_bfloat16 g_h1l[(size_t)NNODES * 2 * DIM];
__device__ __align__(16) __nv_bfloat16 g_w1p[LAYERS * 2 * 16 * B_STAGE];
__device__ __align__(16) __nv_bfloat16 g_w2p[LAYERS * 32 * B_STAGE];
__device__ __align__(16) float g_sum[DIM];
__device__ __align__(16) float g_sumsq[DIM];
__device__ __align__(16) float g_scale[DIM];
__device__ __align__(16) float g_shift[DIM];

// ---------------- helpers ----------------
__device__ __forceinline__ uint32_t cvta_s(const void* p) {
    return (uint32_t)__cvta_generic_to_shared(p);
}
__device__ __forceinline__ uint32_t bpack(__nv_bfloat16 a, __nv_bfloat16 b) {
    __nv_bfloat162 t(a, b);
    return reinterpret_cast<uint32_t&>(t);
}
__device__ __forceinline__ void split4(float4 v, uint2& hi, uint2& lo) {
    float a[4] = {v.x, v.y, v.z, v.w};
    __nv_bfloat16 h[4], l[4];
#pragma unroll
    for (int j = 0; j < 4; j++) {
        h[j] = __float2bfloat16(a[j]);
        l[j] = __float2bfloat16(a[j] - __bfloat162float(h[j]));
    }
    hi = make_uint2(bpack(h[0], h[1]), bpack(h[2], h[3]));
    lo = make_uint2(bpack(l[0], l[1]), bpack(l[2], l[3]));
}
__device__ __forceinline__ void ldsm4(uint32_t r[4], uint32_t a) {
    asm volatile("ldmatrix.sync.aligned.m8n8.x4.shared.b16 {%0,%1,%2,%3}, [%4];"
                 : "=r"(r[0]), "=r"(r[1]), "=r"(r[2]), "=r"(r[3]) : "r"(a));
}
__device__ __forceinline__ void ldsm4t(uint32_t r[4], uint32_t a) {
    asm volatile("ldmatrix.sync.aligned.m8n8.x4.trans.shared.b16 {%0,%1,%2,%3}, [%4];"
                 : "=r"(r[0]), "=r"(r[1]), "=r"(r[2]), "=r"(r[3]) : "r"(a));
}
__device__ __forceinline__ void mma_bf16(float c[4], const uint32_t a[4], const uint32_t b[2]) {
    asm volatile("mma.sync.aligned.m16n8k16.row.col.f32.bf16.bf16.f32 "
                 "{%0,%1,%2,%3}, {%4,%5,%6,%7}, {%8,%9}, {%0,%1,%2,%3};"
                 : "+f"(c[0]), "+f"(c[1]), "+f"(c[2]), "+f"(c[3])
                 : "r"(a[0]), "r"(a[1]), "r"(a[2]), "r"(a[3]), "r"(b[0]), "r"(b[1]));
}
__device__ __forceinline__ void cp16(uint32_t dst, const void* src, bool pred) {
    int sz = pred ? 16 : 0;
    asm volatile("cp.async.cg.shared.global [%0], [%1], 16, %2;"
                 :: "r"(dst), "l"(src), "r"(sz));
}
__device__ __forceinline__ void cp_commit() { asm volatile("cp.async.commit_group;"); }
__device__ __forceinline__ void mbar_init(uint32_t a, uint32_t cnt) {
    asm volatile("mbarrier.init.shared.b64 [%0], %1;" :: "r"(a), "r"(cnt) : "memory");
}
__device__ __forceinline__ void mbar_expect(uint32_t a, uint32_t tx) {
    asm volatile("mbarrier.arrive.expect_tx.shared.b64 _, [%0], %1;"
                 :: "r"(a), "r"(tx) : "memory");
}
__device__ __forceinline__ void bulk_g2s(uint32_t dst, const void* src, uint32_t bytes,
                                         uint32_t bar) {
    asm volatile("cp.async.bulk.shared::cluster.global.mbarrier::complete_tx::bytes "
                 "[%0], [%1], %2, [%3];"
                 :: "r"(dst), "l"(src), "r"(bytes), "r"(bar) : "memory");
}
__device__ __forceinline__ void mbar_wait_acq(uint32_t bar, uint32_t ph) {
    asm volatile("{\n\t.reg .pred P;\n\t"
                 "W%=:\n\t"
                 "mbarrier.try_wait.parity.acquire.cta.shared::cta.b64 P, [%0], %1;\n\t"
                 "@P bra D%=;\n\t"
                 "bra W%=;\n\t"
                 "D%=:\n\t}"
                 :: "r"(bar), "r"(ph) : "memory");
}

// ---------------- init nodes (+layer0 agg) + convert weights ----------------
#define C1TOT (LAYERS * 256 * 128)
#define C2TOT (LAYERS * 512 * 64)
__global__ void init_nodes(const int* __restrict__ x,
                           const float* __restrict__ xe1,
                           const float* __restrict__ xe2,
                           const float* __restrict__ W1,
                           const float* __restrict__ W2,
                           const float* __restrict__ e1self0,
                           const float* __restrict__ e2self0) {
    int t = blockIdx.x * blockDim.x + threadIdx.x;
    if (t < DIM) { g_sum[t] = 0.f; g_sumsq[t] = 0.f; }
    if (t < C1TOT) {
        int l = t / (256 * 128);
        int r = t % (256 * 128);
        int k = r >> 7;
        int n = (r & 127) * 4;
        float4 v = *(const float4*)(W1 + ((size_t)l * 256 + k) * 512 + n);
        uint2 hi, lo;
        split4(v, hi, lo);
        int xh = n >> 8, st = k >> 4, row = k & 15, c = n & 255;
        size_t base = (((size_t)l * 2 + xh) * 16 + st) * B_STAGE + row * BPITCH + c;
        *(uint2*)(g_w1p + base) = hi;
        *(uint2*)(g_w1p + base + B_PLANE) = lo;
    } else if (t < C1TOT + C2TOT) {
        int u = t - C1TOT;
        int l = u / (512 * 64);
        int r = u % (512 * 64);
        int k = r >> 6;
        int n = (r & 63) * 4;
        float4 v = *(const float4*)(W2 + ((size_t)l * 512 + k) * 256 + n);
        uint2 hi, lo;
        split4(v, hi, lo);
        int st = k >> 4, row = k & 15;
        size_t base = ((size_t)l * 32 + st) * B_STAGE + row * BPITCH + n;
        *(uint2*)(g_w2p + base) = hi;
        *(uint2*)(g_w2p + base + B_PLANE) = lo;
    }
    if (t >= NNODES * D4) return;
    int n_ = t / D4, c = t % D4;
    int i0 = x[2 * n_ + 0];
    int i1 = x[2 * n_ + 1];
    float4 a = ((const float4*)(xe1 + (size_t)i0 * DIM))[c];
    float4 b = ((const float4*)(xe2 + (size_t)i1 * DIM))[c];
    float4 r;
    r.x = a.x + b.x; r.y = a.y + b.y; r.z = a.z + b.z; r.w = a.w + b.w;
    ((float4*)g_cur)[t] = r;
    // layer-0 agg = cur + self-emb (fused; saves a full cur re-read)
    float4 s1 = __ldg(&((const float4*)e1self0)[c]);
    float4 s2 = __ldg(&((const float4*)e2self0)[c]);
    r.x += s1.x + s2.x; r.y += s1.y + s2.y; r.z += s1.z + s2.z; r.w += s1.w + s2.w;
    ((float4*)g_agg)[t] = r;
}

// ---------------- layers>=1: agg = relu(bn(h)) + self-emb ----------------
__global__ void agg_self_bn(const float* __restrict__ e1self,
                            const float* __restrict__ e2self) {
    int t = blockIdx.x * blockDim.x + threadIdx.x;
    if (t >= NNODES * D4) return;
    int c = t % D4;
    float4 v = ((const float4*)g_h)[t];
    float4 sc = ((const float4*)g_scale)[c];
    float4 sh = ((const float4*)g_shift)[c];
    float4 a = __ldg(&((const float4*)e1self)[c]);
    float4 b = __ldg(&((const float4*)e2self)[c]);
    float4 r;
    r.x = fmaxf(v.x * sc.x + sh.x, 0.f) + a.x + b.x;
    r.y = fmaxf(v.y * sc.y + sh.y, 0.f) + a.y + b.y;
    r.z = fmaxf(v.z * sc.z + sh.z, 0.f) + a.z + b.z;
    r.w = fmaxf(v.w * sc.w + sh.w, 0.f) + a.w + b.w;
    ((float4*)g_agg)[t] = r;
}

// ---------------- edge messages ----------------
template <bool BN_>
__global__ void edge_msg(const int* __restrict__ ei,
                         const int* __restrict__ ea,
                         const float* __restrict__ ee1,
                         const float* __restrict__ ee2) {
    int gtid = blockIdx.x * blockDim.x + threadIdx.x;
    int e = gtid >> 5;
    int lane = gtid & 31;
    if (e >= NEDGES) return;
    int src = ei[e];
    int dst = ei[NEDGES + e];
    int a0 = ea[2 * e + 0];
    int a1 = ea[2 * e + 1];
    const float4* sp = (const float4*)((BN_ ? g_h : g_cur) + (size_t)src * DIM);
    const float4* e1p = (const float4*)(ee1 + (size_t)a0 * DIM);
    const float4* e2p = (const float4*)(ee2 + (size_t)a1 * DIM);
    float* dp = g_agg + (size_t)dst * DIM;
#pragma unroll
    for (int j = 0; j < 2; j++) {
        int c = lane + j * 32;
        float4 v = sp[c];
        if (BN_) {
            float4 sc = __ldg(&((const float4*)g_scale)[c]);
            float4 sh = __ldg(&((const float4*)g_shift)[c]);
            v.x = fmaxf(v.x * sc.x + sh.x, 0.f);
            v.y = fmaxf(v.y * sc.y + sh.y, 0.f);
            v.z = fmaxf(v.z * sc.z + sh.z, 0.f);
            v.w = fmaxf(v.w * sc.w + sh.w, 0.f);
        }
        float4 w = __ldg(&e1p[c]);
        float4 u = __ldg(&e2p[c]);
        v.x += w.x + u.x; v.y += w.y + u.y; v.z += w.z + u.z; v.w += w.w + u.w;
        asm volatile("red.global.add.v4.f32 [%0], {%1, %2, %3, %4};"
                     :: "l"(dp + c * 4), "f"(v.x), "f"(v.y), "f"(v.z), "f"(v.w)
                     : "memory");
    }
}

// -------- compute one BK=16 stage (R9 pairing) --------
__device__ __forceinline__ void gemm_stage_compute(
    uint32_t sAb, uint32_t sBb, int aBuf, int bBuf,
    int aR, int aKb, int bK, int bNl, int warpN,
    float acc[2][8][4]) {
    uint32_t af[2][2][4];
#pragma unroll
    for (int mi = 0; mi < 2; mi++)
#pragma unroll
        for (int p = 0; p < 2; p++) {
            uint32_t addr = sAb +
                (uint32_t)((aBuf * A_STAGE + p * A_PLANE + (aR + mi * 16) * APITCH) * 2 + aKb);
            ldsm4(af[mi][p], addr);
        }
#pragma unroll
    for (int gp = 0; gp < 2; gp++) {
        uint32_t bh[2][4], bl[2][4];
#pragma unroll
        for (int q = 0; q < 2; q++) {
            int g = gp * 2 + q;
            int n0 = warpN * 64 + g * 16 + bNl;
            ldsm4t(bh[q], sBb + (uint32_t)((bBuf * B_STAGE + bK * BPITCH + n0) * 2));
            ldsm4t(bl[q], sBb + (uint32_t)((bBuf * B_STAGE + B_PLANE + bK * BPITCH + n0) * 2));
        }
#pragma unroll
        for (int q = 0; q < 2; q++)
#pragma unroll
            for (int mi = 0; mi < 2; mi++)
#pragma unroll
                for (int nn = 0; nn < 2; nn++)
                    mma_bf16(acc[mi][(gp * 2 + q) * 2 + nn], af[mi][0], &bh[q][nn * 2]);
#pragma unroll
        for (int q = 0; q < 2; q++)
#pragma unroll
            for (int mi = 0; mi < 2; mi++)
#pragma unroll
                for (int nn = 0; nn < 2; nn++)
                    mma_bf16(acc[mi][(gp * 2 + q) * 2 + nn], af[mi][0], &bl[q][nn * 2]);
#pragma unroll
        for (int q = 0; q < 2; q++)
#pragma unroll
            for (int mi = 0; mi < 2; mi++)
#pragma unroll
                for (int nn = 0; nn < 2; nn++)
                    mma_bf16(acc[mi][(gp * 2 + q) * 2 + nn], af[mi][1], &bh[q][nn * 2]);
    }
}

// ================= GEMM1 (frozen R14 config) =================
__global__ __launch_bounds__(256, 2)
void gemm1(const float* __restrict__ A,
           const __nv_bfloat16* __restrict__ Bp,
           const float* __restrict__ bias,
           __nv_bfloat16* __restrict__ Ch, __nv_bfloat16* __restrict__ Cl,
           int M, int N, int K) {
    extern __shared__ __align__(16) char dynsm[];
    __shared__ __align__(8) uint64_t sbar[B_RING];
    const uint32_t sAb = cvta_s(dynsm);
    const uint32_t sBb = sAb + 3 * A_STAGE * 2;
    const int tid  = threadIdx.x;
    const int lane = tid & 31;
    const int warp = tid >> 5;
    const int warpM = warp & 1;
    const int warpN = warp >> 1;
    const int rowBase = blockIdx.y * BM;
    const int colBase = blockIdx.x * BN;
    const int S = K / BK;   // 16

    const char* Bsrc = (const char*)(Bp + (size_t)blockIdx.x * 16 * B_STAGE);

    const int aR  = warpM * 32 + (lane & 7) + ((lane >> 3) & 1) * 8;
    const int aKb = (lane >> 4) * 16;
    const int bK  = (lane & 7) + ((lane >> 3) & 1) * 8;
    const int bNl = ((lane >> 4) & 1) * 8;

    const int aRow = tid >> 2;
    const int aC4  = (tid & 3) * 4;
    const bool aOk = (rowBase + aRow) < M;
    const float* aPtr = A + (size_t)(rowBase + aRow) * K + aC4;
    const uint32_t aOffBase = (uint32_t)(aRow * APITCH + aC4) * 2;

    float acc[2][8][4];
#pragma unroll
    for (int i = 0; i < 2; i++)
#pragma unroll
        for (int j = 0; j < 8; j++)
#pragma unroll
            for (int k = 0; k < 4; k++) acc[i][j][k] = 0.f;

    if (tid == 0) {
#pragma unroll
        for (int i = 0; i < B_RING; i++) mbar_init(cvta_s(&sbar[i]), 1);
    }

    float4 aV = aOk ? *(const float4*)(aPtr) : make_float4(0, 0, 0, 0);
    {
        uint2 hi, lo;
        split4(aV, hi, lo);
        *(uint2*)(dynsm + aOffBase) = hi;
        *(uint2*)(dynsm + aOffBase + A_PLANE * 2) = lo;
    }
    aV = aOk ? *(const float4*)(aPtr + BK) : make_float4(0, 0, 0, 0);
    if (tid == 0) {
#pragma unroll
        for (int st = 0; st < 3; st++) {
            mbar_expect(cvta_s(&sbar[st]), BBYTES);
            bulk_g2s(sBb + st * BBYTES, Bsrc + (size_t)st * BBYTES, BBYTES, cvta_s(&sbar[st]));
        }
    }

    for (int s = 0; s < S; s++) {
        int aBuf = s & 1;
        int bBuf = s & 3;
        __syncthreads();
        if (s + 1 < S) {
            uint32_t off = (uint32_t)((aBuf ^ 1) * A_STAGE) * 2 + aOffBase;
            uint2 hi, lo;
            split4(aV, hi, lo);
            *(uint2*)(dynsm + off) = hi;
            *(uint2*)(dynsm + off + A_PLANE * 2) = lo;
            if (s + 2 < S)
                aV = aOk ? *(const float4*)(aPtr + (s + 2) * BK) : make_float4(0, 0, 0, 0);
        }
        if (tid == 0 && s + 3 < S) {
            int st = s + 3, rb = st & 3;
            mbar_expect(cvta_s(&sbar[rb]), BBYTES);
            bulk_g2s(sBb + rb * BBYTES, Bsrc + (size_t)st * BBYTES, BBYTES, cvta_s(&sbar[rb]));
        }
        mbar_wait_acq(cvta_s(&sbar[bBuf]), (s >> 2) & 1);
        gemm_stage_compute(sAb, sBb, aBuf, bBuf, aR, aKb, bK, bNl, warpN, acc);
    }

    const int r0b = rowBase + warpM * 32 + (lane >> 2);
    const int cb  = colBase + warpN * 64 + (lane & 3) * 2;
    float bb[16];
#pragma unroll
    for (int ni = 0; ni < 8; ni++) {
        bb[2 * ni]     = __ldg(&bias[cb + ni * 8]);
        bb[2 * ni + 1] = __ldg(&bias[cb + ni * 8 + 1]);
    }
#pragma unroll
    for (int mi = 0; mi < 2; mi++) {
        int r0 = r0b + mi * 16;
        int r1 = r0 + 8;
#pragma unroll
        for (int ni = 0; ni < 8; ni++) {
            int c = cb + ni * 8;
            float2 v0 = make_float2(fmaxf(acc[mi][ni][0] + bb[2 * ni], 0.f),
                                    fmaxf(acc[mi][ni][1] + bb[2 * ni + 1], 0.f));
            float2 v1 = make_float2(fmaxf(acc[mi][ni][2] + bb[2 * ni], 0.f),
                                    fmaxf(acc[mi][ni][3] + bb[2 * ni + 1], 0.f));
            if (r0 < M) {
                __nv_bfloat16 hx = __float2bfloat16(v0.x), hy = __float2bfloat16(v0.y);
                *(uint32_t*)(Ch + (size_t)r0 * N + c) = bpack(hx, hy);
                *(uint32_t*)(Cl + (size_t)r0 * N + c) =
                    bpack(__float2bfloat16(v0.x - __bfloat162float(hx)),
                          __float2bfloat16(v0.y - __bfloat162float(hy)));
            }
            if (r1 < M) {
                __nv_bfloat16 hx = __float2bfloat16(v1.x), hy = __float2bfloat16(v1.y);
                *(uint32_t*)(Ch + (size_t)r1 * N + c) = bpack(hx, hy);
                *(uint32_t*)(Cl + (size_t)r1 * N + c) =
                    bpack(__float2bfloat16(v1.x - __bfloat162float(hx)),
                          __float2bfloat16(v1.y - __bfloat162float(hy)));
            }
        }
    }
}

// ================= GEMM2 (frozen R14 loop; leaner stats epilogue) =================
__device__ __forceinline__ void stage_load_A2(
    uint32_t sAb, int buf,
    const __nv_bfloat16* Ah, const __nv_bfloat16* Al,
    int rowBase, int kOff, int K, int M, int tid) {
    int plane = tid >> 7;
    int rem = tid & 127;
    int row = rem >> 1, c8 = (rem & 1) * 8;
    const __nv_bfloat16* src = (plane ? Al : Ah) + (size_t)(rowBase + row) * K + kOff + c8;
    uint32_t dst = sAb + (uint32_t)(buf * A_STAGE + plane * A_PLANE + row * APITCH + c8) * 2;
    cp16(dst, src, (rowBase + row) < M);
}

template <bool FUSE_STATS>
__global__ __launch_bounds__(256, 2)
void gemm2(const __nv_bfloat16* __restrict__ Ah, const __nv_bfloat16* __restrict__ Al,
           const __nv_bfloat16* __restrict__ Bp,
           const float* __restrict__ bias, float* __restrict__ Cf,
           int M, int N, int K) {
    extern __shared__ __align__(16) char dynsm[];
    __shared__ float sStat[512];
    __shared__ __align__(8) uint64_t sbar[B_RING];
    const uint32_t sAb = cvta_s(dynsm);
    const uint32_t sBb = sAb + 3 * A_STAGE * 2;
    const int tid  = threadIdx.x;
    const int lane = tid & 31;
    const int warp = tid >> 5;
    const int warpM = warp & 1;
    const int warpN = warp >> 1;
    const int rowBase = blockIdx.y * BM;
    const int colBase = blockIdx.x * BN;
    const int S = K / BK;   // 32

    const char* Bsrc = (const char*)Bp;

    if (FUSE_STATS) {
        sStat[tid] = 0.f;
        sStat[256 + tid] = 0.f;
    }

    const int aR  = warpM * 32 + (lane & 7) + ((lane >> 3) & 1) * 8;
    const int aKb = (lane >> 4) * 16;
    const int bK  = (lane & 7) + ((lane >> 3) & 1) * 8;
    const int bNl = ((lane >> 4) & 1) * 8;

    float acc[2][8][4];
#pragma unroll
    for (int i = 0; i < 2; i++)
#pragma unroll
        for (int j = 0; j < 8; j++)
#pragma unroll
            for (int k = 0; k < 4; k++) acc[i][j][k] = 0.f;

    if (tid == 0) {
#pragma unroll
        for (int i = 0; i < B_RING; i++) mbar_init(cvta_s(&sbar[i]), 1);
    }

    stage_load_A2(sAb, 0, Ah, Al, rowBase, 0, K, M, tid);
    cp_commit();
    stage_load_A2(sAb, 1, Ah, Al, rowBase, BK, K, M, tid);
    cp_commit();
    if (tid == 0) {
#pragma unroll
        for (int st = 0; st < 3; st++) {
            mbar_expect(cvta_s(&sbar[st]), BBYTES);
            bulk_g2s(sBb + st * BBYTES, Bsrc + (size_t)st * BBYTES, BBYTES, cvta_s(&sbar[st]));
        }
    }

    for (int s = 0; s < S; s++) {
        int aBuf = s % 3;
        int bBuf = s & 3;
        if (s + 1 < S) asm volatile("cp.async.wait_group 1;");
        else           asm volatile("cp.async.wait_group 0;");
        __syncthreads();
        if (s + 2 < S) {
            stage_load_A2(sAb, (s + 2) % 3, Ah, Al, rowBase, (s + 2) * BK, K, M, tid);
            cp_commit();
        }
        if (tid == 0 && s + 3 < S) {
            int st = s + 3, rb = st & 3;
            mbar_expect(cvta_s(&sbar[rb]), BBYTES);
            bulk_g2s(sBb + rb * BBYTES, Bsrc + (size_t)st * BBYTES, BBYTES, cvta_s(&sbar[rb]));
        }
        mbar_wait_acq(cvta_s(&sbar[bBuf]), (s >> 2) & 1);
        gemm_stage_compute(sAb, sBb, aBuf, bBuf, aR, aKb, bK, bNl, warpN, acc);
    }

    const int r0b = rowBase + warpM * 32 + (lane >> 2);
    const int cb  = colBase + warpN * 64 + (lane & 3) * 2;
    float bb[16];
#pragma unroll
    for (int ni = 0; ni < 8; ni++) {
        bb[2 * ni]     = __ldg(&bias[cb + ni * 8]);
        bb[2 * ni + 1] = __ldg(&bias[cb + ni * 8 + 1]);
    }
    // column-partial stats combined over mi before shfl (halves shfl work)
    float csum[8][2], csq[8][2];
#pragma unroll
    for (int mi = 0; mi < 2; mi++) {
        int r0 = r0b + mi * 16;
        int r1 = r0 + 8;
#pragma unroll
        for (int ni = 0; ni < 8; ni++) {
            int c = cb + ni * 8;
            float2 v0 = make_float2(acc[mi][ni][0] + bb[2 * ni], acc[mi][ni][1] + bb[2 * ni + 1]);
            float2 v1 = make_float2(acc[mi][ni][2] + bb[2 * ni], acc[mi][ni][3] + bb[2 * ni + 1]);
            if (FUSE_STATS) {
                float ax = (r0 < M) ? v0.x : 0.f;
                float ay = (r0 < M) ? v0.y : 0.f;
                float bx2 = (r1 < M) ? v1.x : 0.f;
                float by2 = (r1 < M) ? v1.y : 0.f;
                float s0 = ax + bx2, s1 = ay + by2;
                float q0 = ax * ax + bx2 * bx2, q1 = ay * ay + by2 * by2;
                if (mi == 0) {
                    csum[ni][0] = s0; csum[ni][1] = s1;
                    csq[ni][0] = q0;  csq[ni][1] = q1;
                } else {
                    csum[ni][0] += s0; csum[ni][1] += s1;
                    csq[ni][0] += q0;  csq[ni][1] += q1;
                }
            }
            if (r0 < M) *(float2*)(Cf + (size_t)r0 * N + c) = v0;
            if (r1 < M) *(float2*)(Cf + (size_t)r1 * N + c) = v1;
        }
    }
    if (FUSE_STATS) {
#pragma unroll
        for (int ni = 0; ni < 8; ni++) {
            float s0 = csum[ni][0], s1 = csum[ni][1];
            float q0 = csq[ni][0],  q1 = csq[ni][1];
#pragma unroll
            for (int off = 4; off <= 16; off <<= 1) {
                s0 += __shfl_xor_sync(0xFFFFFFFF, s0, off);
                s1 += __shfl_xor_sync(0xFFFFFFFF, s1, off);
                q0 += __shfl_xor_sync(0xFFFFFFFF, q0, off);
                q1 += __shfl_xor_sync(0xFFFFFFFF, q1, off);
            }
            if ((lane >> 2) == 0) {
                int c = cb + ni * 8 - colBase;
                atomicAdd(&sStat[c], s0);
                atomicAdd(&sStat[c + 1], s1);
                atomicAdd(&sStat[256 + c], q0);
                atomicAdd(&sStat[256 + c + 1], q1);
            }
        }
        __syncthreads();
        atomicAdd(&g_sum[tid], sStat[tid]);
        atomicAdd(&g_sumsq[tid], sStat[256 + tid]);
    }
}

// ---------------- BN finalize (+ re-zero for next layer) ----------------
__global__ void bn_finalize(const float* __restrict__ gamma,
                            const float* __restrict__ beta) {
    int d = threadIdx.x;
    float mean = g_sum[d] * (1.0f / NNODES);
    float var = g_sumsq[d] * (1.0f / NNODES) - mean * mean;
    float sc = gamma[d] * rsqrtf(var + 1e-5f);
    g_scale[d] = sc;
    g_shift[d] = beta[d] - mean * sc;
    g_sum[d] = 0.f;
    g_sumsq[d] = 0.f;
}

// ---------------- launch ----------------
extern "C" void kernel_launch(void* const* d_in, const int* in_sizes, int n_in,
                              void* d_out, int out_size) {
    const int*   x   = (const int*)d_in[0];
    const int*   ei  = (const int*)d_in[1];
    const int*   ea  = (const int*)d_in[2];
    const float* xe1 = (const float*)d_in[3];
    const float* xe2 = (const float*)d_in[4];
    const float* ee1 = (const float*)d_in[5];
    const float* ee2 = (const float*)d_in[6];
    const float* W1  = (const float*)d_in[7];
    const float* b1  = (const float*)d_in[8];
    const float* W2  = (const float*)d_in[9];
    const float* b2  = (const float*)d_in[10];
    const float* gam = (const float*)d_in[11];
    const float* bet = (const float*)d_in[12];
    float* out = (float*)d_out;

    __nv_bfloat16 *p_h1h, *p_h1l, *p_w1p, *p_w2p;
    float *p_h, *p_agg;
    cudaGetSymbolAddress((void**)&p_h1h, g_h1h);
    cudaGetSymbolAddress((void**)&p_h1l, g_h1l);
    cudaGetSymbolAddress((void**)&p_w1p, g_w1p);
    cudaGetSymbolAddress((void**)&p_w2p, g_w2p);
    cudaGetSymbolAddress((void**)&p_h,   g_h);
    cudaGetSymbolAddress((void**)&p_agg, g_agg);

    cudaFuncSetAttribute(gemm1, cudaFuncAttributeMaxDynamicSharedMemorySize, SMEM_G1);
    cudaFuncSetAttribute(gemm2<true>, cudaFuncAttributeMaxDynamicSharedMemorySize, SMEM_G2);
    cudaFuncSetAttribute(gemm2<false>, cudaFuncAttributeMaxDynamicSharedMemorySize, SMEM_G2);

    const int ELEM_BLOCKS = (NNODES * D4 + 255) / 256;
    const int EDGE_BLOCKS = (NEDGES * 32 + 255) / 256;
    const int MB = (NNODES + BM - 1) / BM;

    // layer-0 self-emb pointers for the fused init
    const float* e1l0 = ee1 + 4 * DIM;
    const float* e2l0 = ee2;
    init_nodes<<<ELEM_BLOCKS, 256>>>(x, xe1, xe2, W1, W2, e1l0, e2l0);

    for (int l = 0; l < LAYERS; l++) {
        const float* e1l = ee1 + (size_t)l * 6 * DIM;
        const float* e2l = ee2 + (size_t)l * 3 * DIM;

        if (l == 0) {
            edge_msg<false><<<EDGE_BLOCKS, 256>>>(ei, ea, e1l, e2l);
        } else {
            agg_self_bn<<<ELEM_BLOCKS, 256>>>(e1l + 4 * DIM, e2l);
            edge_msg<true><<<EDGE_BLOCKS, 256>>>(ei, ea, e1l, e2l);
        }

        gemm1<<<dim3(2, MB), 256, SMEM_G1>>>(
            p_agg,
            p_w1p + (size_t)l * 2 * 16 * B_STAGE,
            b1 + (size_t)l * 2 * DIM,
            p_h1h, p_h1l, NNODES, 2 * DIM, DIM);

        if (l < LAYERS - 1) {
            gemm2<true><<<dim3(1, MB), 256, SMEM_G2>>>(
                p_h1h, p_h1l,
                p_w2p + (size_t)l * 32 * B_STAGE,
                b2 + (size_t)l * DIM, p_h, NNODES, DIM, 2 * DIM);
            bn_finalize<<<1, 256>>>(gam + (size_t)l * DIM, bet + (size_t)l * DIM);
        } else {
            gemm2<false><<<dim3(1, MB), 256, SMEM_G2>>>(
                p_h1h, p_h1l,
                p_w2p + (size_t)l * 32 * B_STAGE,
                b2 + (size_t)l * DIM, out, NNODES, DIM, 2 * DIM);
        }
    }
}